// round 1
// baseline (speedup 1.0000x reference)
#include <cuda_runtime.h>
#include <cstdint>

namespace {
constexpr int kS = 2048;
constexpr int kD = 64;
constexpr int BM = 64;     // query rows per CTA (4 warps x 16)
constexpr int BN = 32;     // kv rows per iteration
constexpr int NW = 4;
constexpr int NT = 128;
constexpr int LDK = 72;    // padded smem row stride (floats) for K/V tiles
constexpr int LDP = 36;    // padded smem row stride (floats) for P tiles

__device__ __forceinline__ float tf32f(float x) {
  uint32_t u;
  asm("cvt.rna.tf32.f32 %0, %1;" : "=r"(u) : "f"(x));
  return __uint_as_float(u);
}

__device__ __forceinline__ void mma8(float c[4], const uint32_t a[4],
                                     uint32_t b0, uint32_t b1) {
  asm volatile(
      "mma.sync.aligned.m16n8k8.row.col.f32.tf32.tf32.f32 "
      "{%0,%1,%2,%3}, {%4,%5,%6,%7}, {%8,%9}, {%0,%1,%2,%3};\n"
      : "+f"(c[0]), "+f"(c[1]), "+f"(c[2]), "+f"(c[3])
      : "r"(a[0]), "r"(a[1]), "r"(a[2]), "r"(a[3]), "r"(b0), "r"(b1));
}
}  // namespace

__global__ void __launch_bounds__(NT) attn_fwd(const float* __restrict__ Qg,
                                               const float* __restrict__ Kg,
                                               const float* __restrict__ Vg,
                                               float* __restrict__ Og) {
  const int bh = blockIdx.y;
  const int mBase = blockIdx.x * BM;
  const float* Qp = Qg + ((size_t)bh * kS + mBase) * kD;
  const float* Kp = Kg + (size_t)bh * kS * kD;
  const float* Vp = Vg + (size_t)bh * kS * kD;
  float* Op = Og + ((size_t)bh * kS + mBase) * kD;

  const int tid = threadIdx.x;
  const int w = tid >> 5;
  const int lane = tid & 31;
  const int gid = lane >> 2;  // groupID (row within 8)
  const int tig = lane & 3;   // thread-in-group (col quad)

  __shared__ __align__(16) float sKV[4 * BN * LDK];  // Khi | Klo | Vhi | Vlo
  __shared__ __align__(16) float sP[NW * 16 * LDP];
  float* sKhi = sKV;
  float* sKlo = sKV + BN * LDK;
  float* sVhi = sKV + 2 * BN * LDK;
  float* sVlo = sKV + 3 * BN * LDK;

  // ---- Stage Q (64x64) into smem (coalesced), then build per-warp A frags
  {
    float* sQ = sKV;  // reuse K region as staging (64*LDK floats)
#pragma unroll
    for (int i = 0; i < BM * kD / NT; ++i) {
      int e = i * NT + tid;
      sQ[(e >> 6) * LDK + (e & 63)] = Qp[e];
    }
  }
  __syncthreads();

  uint32_t qhi[8][4], qlo[8][4];
  {
    const float* sQ = sKV;
    const int r0 = w * 16 + gid;
#pragma unroll
    for (int kc = 0; kc < 8; ++kc) {
      int c = kc * 8 + tig;
      float x[4];
      x[0] = sQ[r0 * LDK + c];
      x[1] = sQ[(r0 + 8) * LDK + c];
      x[2] = sQ[r0 * LDK + c + 4];
      x[3] = sQ[(r0 + 8) * LDK + c + 4];
#pragma unroll
      for (int j = 0; j < 4; ++j) {
        float h = tf32f(x[j]);
        qhi[kc][j] = __float_as_uint(h);
        qlo[kc][j] = __float_as_uint(tf32f(x[j] - h));
      }
    }
  }
  __syncthreads();

  float o[8][4];
#pragma unroll
  for (int dc = 0; dc < 8; ++dc)
#pragma unroll
    for (int j = 0; j < 4; ++j) o[dc][j] = 0.f;
  float m0 = -1e30f, m1 = -1e30f, l0 = 0.f, l1 = 0.f;

  float* sPw = sP + w * 16 * LDP;

  for (int t = 0; t < kS / BN; ++t) {
    const float* Kt = Kp + (size_t)t * BN * kD;
    const float* Vt = Vp + (size_t)t * BN * kD;
    // ---- load K/V tile, split fp32 -> tf32 hi/lo at store time
#pragma unroll
    for (int i = 0; i < BN * kD / NT; ++i) {
      int e = i * NT + tid;
      int r = e >> 6, c = e & 63;
      float kx = Kt[e], vx = Vt[e];
      float kh = tf32f(kx), vh = tf32f(vx);
      sKhi[r * LDK + c] = kh;
      sKlo[r * LDK + c] = tf32f(kx - kh);
      sVhi[r * LDK + c] = vh;
      sVlo[r * LDK + c] = tf32f(vx - vh);
    }
    __syncthreads();

    // ---- S = Q K^T via 3xTF32 (hi*hi + lo*hi + hi*lo)
    float s[4][4];
#pragma unroll
    for (int nc = 0; nc < 4; ++nc)
#pragma unroll
      for (int j = 0; j < 4; ++j) s[nc][j] = 0.f;

#pragma unroll
    for (int nc = 0; nc < 4; ++nc) {
      const int krow = (nc * 8 + gid) * LDK;
#pragma unroll
      for (int kc = 0; kc < 8; ++kc) {
        int c = kc * 8 + tig;
        uint32_t b_h0 = __float_as_uint(sKhi[krow + c]);
        uint32_t b_h1 = __float_as_uint(sKhi[krow + c + 4]);
        uint32_t b_l0 = __float_as_uint(sKlo[krow + c]);
        uint32_t b_l1 = __float_as_uint(sKlo[krow + c + 4]);
        mma8(s[nc], qhi[kc], b_h0, b_h1);
        mma8(s[nc], qlo[kc], b_h0, b_h1);
        mma8(s[nc], qhi[kc], b_l0, b_l1);
      }
    }

    // ---- online softmax (C-layout rows gid and gid+8)
    float rmax0 = s[0][0], rmax1 = s[0][2];
#pragma unroll
    for (int nc = 0; nc < 4; ++nc) {
      rmax0 = fmaxf(rmax0, fmaxf(s[nc][0], s[nc][1]));
      rmax1 = fmaxf(rmax1, fmaxf(s[nc][2], s[nc][3]));
    }
    rmax0 = fmaxf(rmax0, __shfl_xor_sync(0xffffffffu, rmax0, 1));
    rmax0 = fmaxf(rmax0, __shfl_xor_sync(0xffffffffu, rmax0, 2));
    rmax1 = fmaxf(rmax1, __shfl_xor_sync(0xffffffffu, rmax1, 1));
    rmax1 = fmaxf(rmax1, __shfl_xor_sync(0xffffffffu, rmax1, 2));
    float mn0 = fmaxf(m0, rmax0), mn1 = fmaxf(m1, rmax1);
    float a0 = __expf(m0 - mn0), a1 = __expf(m1 - mn1);
    m0 = mn0;
    m1 = mn1;
    float rs0 = 0.f, rs1 = 0.f;
#pragma unroll
    for (int nc = 0; nc < 4; ++nc) {
      s[nc][0] = __expf(s[nc][0] - m0);
      s[nc][1] = __expf(s[nc][1] - m0);
      s[nc][2] = __expf(s[nc][2] - m1);
      s[nc][3] = __expf(s[nc][3] - m1);
      rs0 += s[nc][0] + s[nc][1];
      rs1 += s[nc][2] + s[nc][3];
    }
    rs0 += __shfl_xor_sync(0xffffffffu, rs0, 1);
    rs0 += __shfl_xor_sync(0xffffffffu, rs0, 2);
    rs1 += __shfl_xor_sync(0xffffffffu, rs1, 1);
    rs1 += __shfl_xor_sync(0xffffffffu, rs1, 2);
    l0 = l0 * a0 + rs0;
    l1 = l1 * a1 + rs1;
#pragma unroll
    for (int dc = 0; dc < 8; ++dc) {
      o[dc][0] *= a0;
      o[dc][1] *= a0;
      o[dc][2] *= a1;
      o[dc][3] *= a1;
    }

    // ---- P: C-layout -> smem -> A-layout (per-warp private tile)
#pragma unroll
    for (int nc = 0; nc < 4; ++nc) {
      *(float2*)&sPw[gid * LDP + nc * 8 + 2 * tig] =
          make_float2(s[nc][0], s[nc][1]);
      *(float2*)&sPw[(gid + 8) * LDP + nc * 8 + 2 * tig] =
          make_float2(s[nc][2], s[nc][3]);
    }
    __syncwarp();

    uint32_t phi[4][4], plo[4][4];
#pragma unroll
    for (int kc = 0; kc < 4; ++kc) {
      int c = kc * 8 + tig;
      float x[4];
      x[0] = sPw[gid * LDP + c];
      x[1] = sPw[(gid + 8) * LDP + c];
      x[2] = sPw[gid * LDP + c + 4];
      x[3] = sPw[(gid + 8) * LDP + c + 4];
#pragma unroll
      for (int j = 0; j < 4; ++j) {
        float h = tf32f(x[j]);
        phi[kc][j] = __float_as_uint(h);
        plo[kc][j] = __float_as_uint(tf32f(x[j] - h));
      }
    }

    // ---- O += P V via 3xTF32
#pragma unroll
    for (int dc = 0; dc < 8; ++dc) {
#pragma unroll
      for (int kc = 0; kc < 4; ++kc) {
        int vr = (kc * 8 + tig) * LDK + dc * 8 + gid;
        uint32_t b_h0 = __float_as_uint(sVhi[vr]);
        uint32_t b_h1 = __float_as_uint(sVhi[vr + 4 * LDK]);
        uint32_t b_l0 = __float_as_uint(sVlo[vr]);
        uint32_t b_l1 = __float_as_uint(sVlo[vr + 4 * LDK]);
        mma8(o[dc], phi[kc], b_h0, b_h1);
        mma8(o[dc], plo[kc], b_h0, b_h1);
        mma8(o[dc], phi[kc], b_l0, b_l1);
      }
    }
    __syncthreads();
  }

  // ---- epilogue: normalize and store
  const float inv0 = 1.f / l0, inv1 = 1.f / l1;
  const int r0 = w * 16 + gid;
#pragma unroll
  for (int dc = 0; dc < 8; ++dc) {
    int c = dc * 8 + 2 * tig;
    *(float2*)&Op[r0 * kD + c] = make_float2(o[dc][0] * inv0, o[dc][1] * inv0);
    *(float2*)&Op[(r0 + 8) * kD + c] =
        make_float2(o[dc][2] * inv1, o[dc][3] * inv1);
  }
}

extern "C" void kernel_launch(void* const* d_in, const int* in_sizes, int n_in,
                              void* d_out, int out_size) {
  const float* Q = (const float*)d_in[0];  // input_query
  const float* K = (const float*)d_in[1];  // input_key
  const float* V = (const float*)d_in[2];  // input_value
  float* O = (float*)d_out;
  dim3 grid(kS / BM, 4 * 16);  // 32 M-tiles x 64 (b,h) heads
  attn_fwd<<<grid, NT>>>(Q, K, V, O);
}